// round 15
// baseline (speedup 1.0000x reference)
#include <cuda_runtime.h>
#include <cstdint>
#include <cstring>

#define NS    32768
#define NBITS 64
#define MG    8
#define HID   256
#define NC    100

typedef unsigned long long ull;

// ---------------------------------------------------------------------------
// Threefry-2x32, 20 rounds — bit-exact match of JAX's threefry2x32 primitive.
// ---------------------------------------------------------------------------
__host__ __device__ __forceinline__ void threefry2x32(
    uint32_t k0, uint32_t k1, uint32_t c0, uint32_t c1,
    uint32_t& o0, uint32_t& o1) {
  uint32_t ks2 = k0 ^ k1 ^ 0x1BD11BDAu;
  uint32_t x0 = c0 + k0;
  uint32_t x1 = c1 + k1;
#define TF_RND(r) { x0 += x1; x1 = (x1 << (r)) | (x1 >> (32 - (r))); x1 ^= x0; }
  TF_RND(13) TF_RND(15) TF_RND(26) TF_RND(6)
  x0 += k1;  x1 += ks2 + 1u;
  TF_RND(17) TF_RND(29) TF_RND(16) TF_RND(24)
  x0 += ks2; x1 += k0 + 2u;
  TF_RND(13) TF_RND(15) TF_RND(26) TF_RND(6)
  x0 += k0;  x1 += k1 + 3u;
  TF_RND(17) TF_RND(29) TF_RND(16) TF_RND(24)
  x0 += k1;  x1 += ks2 + 4u;
  TF_RND(13) TF_RND(15) TF_RND(26) TF_RND(6)
  x0 += ks2; x1 += k0 + 5u;
#undef TF_RND
  o0 = x0; o1 = x1;
}

// ---------------------------------------------------------------------------
// Device-global scratch
// ---------------------------------------------------------------------------
__device__ float g_xp  [NS * NBITS];
__device__ float g_xmap[NS * NBITS];
__device__ unsigned char g_target[NS * MG];
__device__ unsigned int  g_xbits[NS * 2];
__device__ int           g_K[NS];
__device__ unsigned char g_act[NS * NC];
__device__ unsigned char g_ct[NC * MG];
__device__ unsigned int  g_cbits[NC * 2];
__device__ double g_mapSum;
__device__ double g_netSum;
__device__ unsigned long long g_hits;
__device__ unsigned long long g_hamSum;
__device__ unsigned long long g_actTot;
__device__ int g_tmode;

__device__ __forceinline__ bool read_tpl(const void* p, int b) {
  if (g_tmode == 0) return ((const unsigned char*)p)[b] != 0;
  return ((const int*)p)[b] != 0;
}

// ---------------------------------------------------------------------------
// Kernel 1: accumulator init + template dtype detect + centroid prep
// ---------------------------------------------------------------------------
__global__ void setup_kernel(const float* __restrict__ cen,
                             const int* __restrict__ perm,
                             const unsigned char* tm, const unsigned char* tr) {
  __shared__ int permS[NBITS];
  int t = threadIdx.x;
  if (t < NBITS) permS[t] = perm[t];
  if (t == 0) {
    g_mapSum = 0.0; g_netSum = 0.0;
    g_hits = 0ull; g_hamSum = 0ull; g_actTot = 0ull;
    int has3F = 0, mis = 0;
    for (int i = 0; i < 64; i++) {
      unsigned char bm = tm[i], br = tr[i];
      if (bm == 0x3F || br == 0x3F) has3F = 1;
      if (i & 3) mis += (bm != 0) + (br != 0);
    }
    g_tmode = has3F ? 1 : (mis ? 0 : 1);
  }
  __syncthreads();
  if (t >= NC) return;
  unsigned int w0 = 0, w1 = 0;
  for (int b = 0; b < NBITS; b++) {
    bool bit = cen[t * NBITS + permS[b]] > 0.f;
    if (bit) { if (b < 32) w0 |= 1u << b; else w1 |= 1u << (b - 32); }
  }
  g_cbits[t * 2 + 0] = w0;
  g_cbits[t * 2 + 1] = w1;
  for (int m = 0; m < MG; m++) {
    unsigned int w = (m < 4) ? w0 : w1;
    g_ct[t * MG + m] = (unsigned char)((w >> ((m & 3) * 8)) & 0xffu);
  }
}

// ---------------------------------------------------------------------------
// Kernel 2: PRNG draws, stable argsort ranks, flips, targets, sign bits.
// ---------------------------------------------------------------------------
__global__ void prep_kernel(const float* __restrict__ x,
                            const int* __restrict__ perm,
                            const void* tmap, const void* traw,
                            uint32_t km0, uint32_t km1,
                            uint32_t kr0, uint32_t kr1) {
  __shared__ float xps[2][NBITS];
  __shared__ unsigned int us[2][2][NBITS];
  __shared__ int permS[NBITS];
  __shared__ int tposS[2][4];
  __shared__ int ranksS[2][2][4];
  __shared__ unsigned int rawb[2][2];
  __shared__ unsigned int xbw[2][2];

  int tid = threadIdx.x;
  if (tid < NBITS) permS[tid] = perm[tid];
  if (tid < 2) {
    const void* tp = (tid == 0) ? tmap : traw;
    int c = 0;
    for (int b = 0; b < NBITS; b++)
      if (read_tpl(tp, b)) { if (c < 4) tposS[tid][c] = b; c++; }
  }
  if (tid < 4) { rawb[tid >> 1][tid & 1] = 0u; xbw[tid >> 1][tid & 1] = 0u; }
  __syncthreads();

  int rid = tid >> 7;
  int sub = tid & 127;
  int op  = sub >> 6;
  int b   = sub & 63;
  int row = blockIdx.x * 2 + rid;

  if (op == 0) xps[rid][b] = x[row * NBITS + permS[b]];
  uint32_t k0 = op ? kr0 : km0;
  uint32_t k1 = op ? kr1 : km1;
  uint32_t o0, o1;
  threefry2x32(k0, k1, 0u, (uint32_t)(row * NBITS + b), o0, o1);
  us[rid][op][b] = (o0 ^ o1) >> 9;
  __syncthreads();

  if (b < 4) {
    int tpos = tposS[op][b];
    unsigned int ut = us[rid][op][tpos];
    int cnt = 0;
    for (int j = 0; j < NBITS; j++) {
      unsigned int uj = us[rid][op][j];
      cnt += (uj < ut) || (uj == ut && j < tpos);
    }
    ranksS[rid][op][b] = cnt;
  }
  __syncthreads();

  float v = xps[rid][b];
  bool flip = (b == ranksS[rid][op][0]) | (b == ranksS[rid][op][1]) |
              (b == ranksS[rid][op][2]) | (b == ranksS[rid][op][3]);
  if (op == 0) {
    g_xp  [row * NBITS + b] = v;
    g_xmap[row * NBITS + b] = flip ? -v : v;
    if (v > 0.f) atomicOr(&xbw[rid][b >> 5], 1u << (b & 31));
  } else {
    bool bit = flip ? (v < 0.f) : (v > 0.f);
    if (bit) atomicOr(&rawb[rid][b >> 5], 1u << (b & 31));
  }
  __syncthreads();

  if (op == 1 && b < MG) {
    unsigned int w = rawb[rid][b >> 2];
    g_target[row * MG + b] = (unsigned char)((w >> ((b & 3) * 8)) & 0xffu);
  }
  if (op == 0 && b < 2) g_xbits[row * 2 + b] = xbw[rid][b];
}

// ---------------------------------------------------------------------------
// Kernel 3: active-class compaction + exact hamming sums. 1 warp / row.
// ---------------------------------------------------------------------------
__global__ void ham_kernel(const int* __restrict__ y) {
  int tid = threadIdx.x, w = tid >> 5, l = tid & 31;
  int row = blockIdx.x * 8 + w;
  unsigned int xb0 = g_xbits[row * 2], xb1 = g_xbits[row * 2 + 1];
  int K = 0;
  unsigned long long hs = 0ull;
  for (int cb = 0; cb < 128; cb += 32) {
    int c = cb + l;
    bool act = (c < NC) && (y[row * NC + c] > 0);
    unsigned int msk = __ballot_sync(0xffffffffu, act);
    if (act) {
      int pos = K + __popc(msk & ((1u << l) - 1u));
      g_act[row * NC + pos] = (unsigned char)c;
      hs += (unsigned long long)(__popc(xb0 ^ g_cbits[c * 2]) +
                                 __popc(xb1 ^ g_cbits[c * 2 + 1]));
    }
    K += __popc(msk);
  }
  if (l == 0) g_K[row] = K;
  for (int o = 16; o; o >>= 1)
    hs += __shfl_xor_sync(0xffffffffu, hs, o);
  if (l == 0) {
    atomicAdd(&g_hamSum, hs);
    atomicAdd(&g_actTot, (unsigned long long)K);
  }
}

// ---------------------------------------------------------------------------
// Kernel 4: fused batched MLP + losses. FFMA2.
// CTA: 512 thr = 16 warps; 64 rows; 2 CTAs/SM (32 warps, occ 50%).
// GEMM2 warp tile 16 rows x 64 cols: rg = w>>2 (rows [16rg,+16)),
//   cg = w&3 (cols [64cg,+64)); lane l owns cols 64cg+2l, +1.
// Per warp-k: 1 LDS64 W + 2 dup movs + 4 broadcast LDS128 h + 16 FFMA2;
//   acc2[8 row-pairs][2 cols] = 32 regs -> __launch_bounds__(512,2).
// hT [k][row] stride 72; logits (64 x 264 = 16896) aliases hT floats < 16896;
//   chunk-31 hT reads are floats >= 248*72 = 17856 -> race-free vs epilogue.
// W2 in 8-k chunks (8KB), 2 buffers, ONE __syncthreads per chunk.
// GEMM1: warp w rows [4w, 4w+4) from x-slice in smem.
// smem 103.4KB -> 2 CTAs/SM.
// ---------------------------------------------------------------------------
#define HSTRIDE  72
#define LSTRIDE  264
#define XSTRIDE  12
#define SM_W1S   0          // 2048
#define SM_B1    2048       // 256
#define SM_B2    2304       // 256
#define SM_XS    2560       // 768 (64 rows * 12)
#define SM_HT    3328       // 18432 (256 k * 72); logits (64*264=16896) aliases
#define SM_W2    21760      // 2 bufs * 2048 (8 k * 256)
#define SM_FLOATS 25856     // 103424 bytes

__device__ __forceinline__ void ffma2(ull& d, ull a, ull b) {
  asm("fma.rn.f32x2 %0, %1, %2, %0;" : "+l"(d) : "l"(a), "l"(b));
}
__device__ __forceinline__ ull dup2(float v) {
  ull r;
  asm("mov.b64 %0, {%1, %1};" : "=l"(r) : "f"(v));
  return r;
}
__device__ __forceinline__ float2 unpack2(ull v) {
  float2 t;
  asm("mov.b64 {%0, %1}, %2;" : "=f"(t.x), "=f"(t.y) : "l"(v));
  return t;
}
__device__ __forceinline__ void cpasync16(float* s, const float* g) {
  unsigned sa = (unsigned)__cvta_generic_to_shared(s);
  asm volatile("cp.async.cg.shared.global [%0], [%1], 16;" :: "r"(sa), "l"(g));
}
__device__ __forceinline__ float fast_rcp(float d) {
  float r = __uint_as_float(0x7EF311C3u - __float_as_uint(d));
  r = r * (2.0f - d * r);
  r = r * (2.0f - d * r);
  r = r * (2.0f - d * r);
  return r;
}

__global__ void __launch_bounds__(512, 2)
mlp_kernel(const float* __restrict__ W1, const float* __restrict__ b1,
           const float* __restrict__ W2, const float* __restrict__ b2) {
  extern __shared__ float sm[];
  float* W1s    = sm + SM_W1S;
  float* b1s    = sm + SM_B1;
  float* b2s    = sm + SM_B2;
  float* xss    = sm + SM_XS;
  float* hT     = sm + SM_HT;
  float* logits = sm + SM_HT;   // alias: hT floats < 16896 dead by epilogue
  float* w2s    = sm + SM_W2;

  int tid = threadIdx.x, w = tid >> 5, l = tid & 31;
  int rg = w >> 2, cg = w & 3;
  int pass = blockIdx.y;
  int row0 = blockIdx.x * 64;
  const float* inp = (pass == 0) ? g_xmap : g_xp;

  double mapAcc = 0.0, netAcc = 0.0;
  unsigned int hitAcc = 0;

  for (int mm = 0; mm < MG; mm++) {
    __syncthreads();   // (a) prev-m logits reads done before hT/W1s overwrite
    {
      const float4* w1p = (const float4*)(W1 + mm * 2048);
      ((float4*)W1s)[tid] = w1p[tid];
      if (tid < 256) {
        b1s[tid] = b1[mm * 256 + tid];
        b2s[tid] = b2[mm * 256 + tid];
      }
      int r = tid >> 3, c = tid & 7;
      if (r < 64) xss[r * XSTRIDE + c] = inp[(row0 + r) * NBITS + mm * 8 + c];
    }
    __syncthreads();   // (b)

    // prefetch chunk 0 of W2 (overlaps GEMM1)
    {
      const float* src = W2 + mm * 65536;
      cpasync16(w2s + tid * 4, src + tid * 4);
      asm volatile("cp.async.commit_group;");
    }

    // ---- GEMM1: warp w computes rows [4w, 4w+4), all 256 k ----
#pragma unroll
    for (int kk = 0; kk < 8; kk++) {
      int k = kk * 32 + l;
      float w1c[8];
#pragma unroll
      for (int s = 0; s < 8; s++) w1c[s] = W1s[s * 256 + k];
      float bk = b1s[k];
#pragma unroll
      for (int rp = 0; rp < 2; rp++) {
        float h2[2];
#pragma unroll
        for (int u = 0; u < 2; u++) {
          int row = 4 * w + 2 * rp + u;
          const float* xb = xss + row * XSTRIDE;
          float4 xa = *(const float4*)(xb);
          float4 xc = *(const float4*)(xb + 4);
          float a = bk;
          a = fmaf(xa.x, w1c[0], a); a = fmaf(xa.y, w1c[1], a);
          a = fmaf(xa.z, w1c[2], a); a = fmaf(xa.w, w1c[3], a);
          a = fmaf(xc.x, w1c[4], a); a = fmaf(xc.y, w1c[5], a);
          a = fmaf(xc.z, w1c[6], a); a = fmaf(xc.w, w1c[7], a);
          float t = __expf(-a);
          float d = 1.0f + fminf(t, 1e30f);
          h2[u] = a * fast_rcp(d);
        }
        *(float2*)(hT + k * HSTRIDE + 4 * w + 2 * rp) =
            make_float2(h2[0], h2[1]);
      }
    }

    // ---- GEMM2: 16 rows x 64 cols per warp; 32 chunks of 8 k;
    //      one __syncthreads per chunk ----
    ull acc2[8][2];
#pragma unroll
    for (int i = 0; i < 8; i++) { acc2[i][0] = 0ull; acc2[i][1] = 0ull; }

    const float* wbase = w2s + 64 * cg + 2 * l;
    const float* hbase = hT + 16 * rg;

    for (int hc = 0; hc < 32; hc++) {
      asm volatile("cp.async.wait_group 0;");
      __syncthreads();   // chunk hc visible; buffer (hc+1)&1 retired by all

      if (hc + 1 < 32) {
        const float* src = W2 + mm * 65536 + (hc + 1) * 2048;
        float* dst = w2s + ((hc + 1) & 1) * 2048;
        cpasync16(dst + tid * 4, src + tid * 4);
        asm volatile("cp.async.commit_group;");
      }

      const float* wch = wbase + (hc & 1) * 2048;
      const float* hb  = hbase + (hc * 8) * HSTRIDE;
#pragma unroll
      for (int kk2 = 0; kk2 < 8; kk2++) {
        float2 wv = *(const float2*)(wch + kk2 * 256);
        ull wd0 = dup2(wv.x), wd1 = dup2(wv.y);
        const float* hk = hb + kk2 * HSTRIDE;
        ulonglong2 hA = *(const ulonglong2*)(hk);       // row pairs 0,1
        ulonglong2 hB = *(const ulonglong2*)(hk + 4);   // row pairs 2,3
        ulonglong2 hC = *(const ulonglong2*)(hk + 8);   // row pairs 4,5
        ulonglong2 hD = *(const ulonglong2*)(hk + 12);  // row pairs 6,7
        ffma2(acc2[0][0], hA.x, wd0); ffma2(acc2[0][1], hA.x, wd1);
        ffma2(acc2[1][0], hA.y, wd0); ffma2(acc2[1][1], hA.y, wd1);
        ffma2(acc2[2][0], hB.x, wd0); ffma2(acc2[2][1], hB.x, wd1);
        ffma2(acc2[3][0], hB.y, wd0); ffma2(acc2[3][1], hB.y, wd1);
        ffma2(acc2[4][0], hC.x, wd0); ffma2(acc2[4][1], hC.x, wd1);
        ffma2(acc2[5][0], hC.y, wd0); ffma2(acc2[5][1], hC.y, wd1);
        ffma2(acc2[6][0], hD.x, wd0); ffma2(acc2[6][1], hD.x, wd1);
        ffma2(acc2[7][0], hD.y, wd0); ffma2(acc2[7][1], hD.y, wd1);
      }
    }

    // ---- epilogue: logits (+bias) -> smem (disjoint from chunk-31 hT) ----
    {
      float2 bcol = *(const float2*)(b2s + 64 * cg + 2 * l);
#pragma unroll
      for (int p = 0; p < 8; p++) {
        float2 c0 = unpack2(acc2[p][0]);   // col 2l:   rows 2p, 2p+1
        float2 c1 = unpack2(acc2[p][1]);   // col 2l+1
        int r0 = 16 * rg + 2 * p;
        *(float2*)(logits + r0 * LSTRIDE + 64 * cg + 2 * l) =
            make_float2(c0.x + bcol.x, c1.x + bcol.y);
        *(float2*)(logits + (r0 + 1) * LSTRIDE + 64 * cg + 2 * l) =
            make_float2(c0.y + bcol.x, c1.y + bcol.y);
      }
    }
    __syncthreads();   // (e) logits complete

    // ---- per-row reductions: warp w owns rows [4w, 4w+4) ----
    for (int i = 0; i < 4; i++) {
      int lrow = w * 4 + i;
      int grow = row0 + lrow;
      float v[8];
      {
        float4 va = *(const float4*)(logits + lrow * LSTRIDE + 8 * l);
        float4 vb = *(const float4*)(logits + lrow * LSTRIDE + 8 * l + 4);
        v[0] = va.x; v[1] = va.y; v[2] = va.z; v[3] = va.w;
        v[4] = vb.x; v[5] = vb.y; v[6] = vb.z; v[7] = vb.w;
      }
      float mx = v[0]; int ai = 8 * l;
#pragma unroll
      for (int j = 1; j < 8; j++)
        if (v[j] > mx) { mx = v[j]; ai = 8 * l + j; }
      for (int o = 16; o; o >>= 1) {
        float vm = __shfl_xor_sync(0xffffffffu, mx, o);
        int   vi = __shfl_xor_sync(0xffffffffu, ai, o);
        if (vm > mx || (vm == mx && vi < ai)) { mx = vm; ai = vi; }
      }
      float se = 0.f;
#pragma unroll
      for (int j = 0; j < 8; j++) se += __expf(v[j] - mx);
      for (int o = 16; o; o >>= 1)
        se += __shfl_xor_sync(0xffffffffu, se, o);
      float lse = mx + __logf(se);
      __syncwarp();

      if (pass == 0) {
        if (l == 0) {
          int tgt = g_target[grow * MG + mm];
          mapAcc += (double)(lse - logits[lrow * LSTRIDE + tgt]);
          hitAcc += (ai == tgt) ? 1u : 0u;
        }
      } else {
        int K = g_K[grow];
        const unsigned char* al2 = g_act + grow * NC;
        double gs = 0.0;
        for (int ci = l; ci < K; ci += 32)
          gs += (double)logits[lrow * LSTRIDE + g_ct[al2[ci] * MG + mm]];
        for (int o = 16; o; o >>= 1)
          gs += __shfl_xor_sync(0xffffffffu, gs, o);
        if (l == 0) netAcc += (double)lse - gs / (double)K;
      }
      __syncwarp();
    }
  }

  if (l == 0) {
    if (pass == 0) {
      atomicAdd(&g_mapSum, mapAcc);
      atomicAdd(&g_hits, (unsigned long long)hitAcc);
    } else {
      atomicAdd(&g_netSum, netAcc);
    }
  }
}

// ---------------------------------------------------------------------------
// Kernel 5: finalize 5 scalars
// ---------------------------------------------------------------------------
__global__ void finalize_kernel(float* out) {
  if (threadIdx.x == 0) {
    double net = g_netSum / (double)NS;
    double map = g_mapSum / (double)NS;
    out[0] = (float)(net + map);
    out[1] = (float)net;
    out[2] = (float)map;
    out[3] = (float)((double)g_hits / ((double)NS * (double)MG));
    out[4] = (float)((double)g_hamSum / (double)g_actTot);
  }
}

// ---------------------------------------------------------------------------
extern "C" void kernel_launch(void* const* d_in, const int* in_sizes, int n_in,
                              void* d_out, int out_size) {
  const float* x    = (const float*)d_in[0];
  const int*   y    = (const int*)  d_in[1];
  const float* cen  = (const float*)d_in[2];
  const int*   perm = (const int*)  d_in[3];
  const void*  tmap = d_in[4];
  const void*  traw = d_in[5];
  const float* W1   = (const float*)d_in[6];
  const float* b1   = (const float*)d_in[7];
  const float* W2   = (const float*)d_in[8];
  const float* b2   = (const float*)d_in[9];
  float* out = (float*)d_out;

  uint32_t km0, km1, kr0, kr1;
  threefry2x32(0u, 1u, 0u, 0u, km0, km1);
  threefry2x32(0u, 1u, 0u, 1u, kr0, kr1);

  cudaFuncSetAttribute(mlp_kernel, cudaFuncAttributeMaxDynamicSharedMemorySize,
                       SM_FLOATS * 4);

  setup_kernel<<<1, 128>>>(cen, perm, (const unsigned char*)tmap,
                           (const unsigned char*)traw);
  prep_kernel<<<NS / 2, 256>>>(x, perm, tmap, traw, km0, km1, kr0, kr1);
  ham_kernel<<<NS / 8, 256>>>(y);
  dim3 grid(NS / 64, 2);
  mlp_kernel<<<grid, 512, SM_FLOATS * 4>>>(W1, b1, W2, b2);
  finalize_kernel<<<1, 32>>>(out);
  (void)in_sizes; (void)n_in; (void)out_size;
}

// round 16
// speedup vs baseline: 1.0302x; 1.0302x over previous
#include <cuda_runtime.h>
#include <cstdint>
#include <cstring>

#define NS    32768
#define NBITS 64
#define MG    8
#define HID   256
#define NC    100

typedef unsigned long long ull;

// ---------------------------------------------------------------------------
// Threefry-2x32, 20 rounds — bit-exact match of JAX's threefry2x32 primitive.
// ---------------------------------------------------------------------------
__host__ __device__ __forceinline__ void threefry2x32(
    uint32_t k0, uint32_t k1, uint32_t c0, uint32_t c1,
    uint32_t& o0, uint32_t& o1) {
  uint32_t ks2 = k0 ^ k1 ^ 0x1BD11BDAu;
  uint32_t x0 = c0 + k0;
  uint32_t x1 = c1 + k1;
#define TF_RND(r) { x0 += x1; x1 = (x1 << (r)) | (x1 >> (32 - (r))); x1 ^= x0; }
  TF_RND(13) TF_RND(15) TF_RND(26) TF_RND(6)
  x0 += k1;  x1 += ks2 + 1u;
  TF_RND(17) TF_RND(29) TF_RND(16) TF_RND(24)
  x0 += ks2; x1 += k0 + 2u;
  TF_RND(13) TF_RND(15) TF_RND(26) TF_RND(6)
  x0 += k0;  x1 += k1 + 3u;
  TF_RND(17) TF_RND(29) TF_RND(16) TF_RND(24)
  x0 += k1;  x1 += ks2 + 4u;
  TF_RND(13) TF_RND(15) TF_RND(26) TF_RND(6)
  x0 += ks2; x1 += k0 + 5u;
#undef TF_RND
  o0 = x0; o1 = x1;
}

// ---------------------------------------------------------------------------
// Device-global scratch
// ---------------------------------------------------------------------------
__device__ float g_xp  [NS * NBITS];
__device__ float g_xmap[NS * NBITS];
__device__ unsigned char g_target[NS * MG];
__device__ unsigned int  g_xbits[NS * 2];
__device__ int           g_K[NS];
__device__ unsigned char g_act[NS * NC];
__device__ unsigned char g_ct[NC * MG];
__device__ unsigned int  g_cbits[NC * 2];
__device__ double g_mapSum;
__device__ double g_netSum;
__device__ unsigned long long g_hits;
__device__ unsigned long long g_hamSum;
__device__ unsigned long long g_actTot;
__device__ int g_tmode;

__device__ __forceinline__ bool read_tpl(const void* p, int b) {
  if (g_tmode == 0) return ((const unsigned char*)p)[b] != 0;
  return ((const int*)p)[b] != 0;
}

// ---------------------------------------------------------------------------
// Kernel 1: accumulator init + template dtype detect + centroid prep
// ---------------------------------------------------------------------------
__global__ void setup_kernel(const float* __restrict__ cen,
                             const int* __restrict__ perm,
                             const unsigned char* tm, const unsigned char* tr) {
  __shared__ int permS[NBITS];
  int t = threadIdx.x;
  if (t < NBITS) permS[t] = perm[t];
  if (t == 0) {
    g_mapSum = 0.0; g_netSum = 0.0;
    g_hits = 0ull; g_hamSum = 0ull; g_actTot = 0ull;
    int has3F = 0, mis = 0;
    for (int i = 0; i < 64; i++) {
      unsigned char bm = tm[i], br = tr[i];
      if (bm == 0x3F || br == 0x3F) has3F = 1;
      if (i & 3) mis += (bm != 0) + (br != 0);
    }
    g_tmode = has3F ? 1 : (mis ? 0 : 1);
  }
  __syncthreads();
  if (t >= NC) return;
  unsigned int w0 = 0, w1 = 0;
  for (int b = 0; b < NBITS; b++) {
    bool bit = cen[t * NBITS + permS[b]] > 0.f;
    if (bit) { if (b < 32) w0 |= 1u << b; else w1 |= 1u << (b - 32); }
  }
  g_cbits[t * 2 + 0] = w0;
  g_cbits[t * 2 + 1] = w1;
  for (int m = 0; m < MG; m++) {
    unsigned int w = (m < 4) ? w0 : w1;
    g_ct[t * MG + m] = (unsigned char)((w >> ((m & 3) * 8)) & 0xffu);
  }
}

// ---------------------------------------------------------------------------
// Kernel 2: PRNG draws, stable argsort ranks, flips, targets, sign bits.
// ---------------------------------------------------------------------------
__global__ void prep_kernel(const float* __restrict__ x,
                            const int* __restrict__ perm,
                            const void* tmap, const void* traw,
                            uint32_t km0, uint32_t km1,
                            uint32_t kr0, uint32_t kr1) {
  __shared__ float xps[2][NBITS];
  __shared__ unsigned int us[2][2][NBITS];
  __shared__ int permS[NBITS];
  __shared__ int tposS[2][4];
  __shared__ int ranksS[2][2][4];
  __shared__ unsigned int rawb[2][2];
  __shared__ unsigned int xbw[2][2];

  int tid = threadIdx.x;
  if (tid < NBITS) permS[tid] = perm[tid];
  if (tid < 2) {
    const void* tp = (tid == 0) ? tmap : traw;
    int c = 0;
    for (int b = 0; b < NBITS; b++)
      if (read_tpl(tp, b)) { if (c < 4) tposS[tid][c] = b; c++; }
  }
  if (tid < 4) { rawb[tid >> 1][tid & 1] = 0u; xbw[tid >> 1][tid & 1] = 0u; }
  __syncthreads();

  int rid = tid >> 7;
  int sub = tid & 127;
  int op  = sub >> 6;
  int b   = sub & 63;
  int row = blockIdx.x * 2 + rid;

  if (op == 0) xps[rid][b] = x[row * NBITS + permS[b]];
  uint32_t k0 = op ? kr0 : km0;
  uint32_t k1 = op ? kr1 : km1;
  uint32_t o0, o1;
  threefry2x32(k0, k1, 0u, (uint32_t)(row * NBITS + b), o0, o1);
  us[rid][op][b] = (o0 ^ o1) >> 9;
  __syncthreads();

  if (b < 4) {
    int tpos = tposS[op][b];
    unsigned int ut = us[rid][op][tpos];
    int cnt = 0;
    for (int j = 0; j < NBITS; j++) {
      unsigned int uj = us[rid][op][j];
      cnt += (uj < ut) || (uj == ut && j < tpos);
    }
    ranksS[rid][op][b] = cnt;
  }
  __syncthreads();

  float v = xps[rid][b];
  bool flip = (b == ranksS[rid][op][0]) | (b == ranksS[rid][op][1]) |
              (b == ranksS[rid][op][2]) | (b == ranksS[rid][op][3]);
  if (op == 0) {
    g_xp  [row * NBITS + b] = v;
    g_xmap[row * NBITS + b] = flip ? -v : v;
    if (v > 0.f) atomicOr(&xbw[rid][b >> 5], 1u << (b & 31));
  } else {
    bool bit = flip ? (v < 0.f) : (v > 0.f);
    if (bit) atomicOr(&rawb[rid][b >> 5], 1u << (b & 31));
  }
  __syncthreads();

  if (op == 1 && b < MG) {
    unsigned int w = rawb[rid][b >> 2];
    g_target[row * MG + b] = (unsigned char)((w >> ((b & 3) * 8)) & 0xffu);
  }
  if (op == 0 && b < 2) g_xbits[row * 2 + b] = xbw[rid][b];
}

// ---------------------------------------------------------------------------
// Kernel 3: active-class compaction + exact hamming sums. 1 warp / row.
// ---------------------------------------------------------------------------
__global__ void ham_kernel(const int* __restrict__ y) {
  int tid = threadIdx.x, w = tid >> 5, l = tid & 31;
  int row = blockIdx.x * 8 + w;
  unsigned int xb0 = g_xbits[row * 2], xb1 = g_xbits[row * 2 + 1];
  int K = 0;
  unsigned long long hs = 0ull;
  for (int cb = 0; cb < 128; cb += 32) {
    int c = cb + l;
    bool act = (c < NC) && (y[row * NC + c] > 0);
    unsigned int msk = __ballot_sync(0xffffffffu, act);
    if (act) {
      int pos = K + __popc(msk & ((1u << l) - 1u));
      g_act[row * NC + pos] = (unsigned char)c;
      hs += (unsigned long long)(__popc(xb0 ^ g_cbits[c * 2]) +
                                 __popc(xb1 ^ g_cbits[c * 2 + 1]));
    }
    K += __popc(msk);
  }
  if (l == 0) g_K[row] = K;
  for (int o = 16; o; o >>= 1)
    hs += __shfl_xor_sync(0xffffffffu, hs, o);
  if (l == 0) {
    atomicAdd(&g_hamSum, hs);
    atomicAdd(&g_actTot, (unsigned long long)K);
  }
}

// ---------------------------------------------------------------------------
// Kernel 4: fused batched MLP + losses. FFMA2, 8 rows x 256 cols per warp.
//
// CTA: 256 thr = 8 warps; 64 rows; 2 CTAs/SM. Warp w owns rows [8w, 8w+8)
//   and ALL 256 cols; lane l owns cols {4l..4l+3} U {128+4l..+3}
//   (both W LDS128 conflict-free).
// Per warp-k: 2 LDS128 W + 8 dup movs + 2 broadcast LDS128 h (4 natural
//   f32x2 row-pairs) + 32 FFMA2. Crossbar 16 wf/warp-k -> 128 wf/CTA-k,
//   exactly matching the 128-cyc fma demand (was 288 wf in R15).
// acc2[4 row-pairs][8 cols] = 64 regs -> __launch_bounds__(256,2).
// Epilogue: NO CTA barrier — warp owns whole rows; reductions from regs,
//   gathers from the warp's own logits rows after __syncwarp.
// hT [k][row] stride 72; logits (64x264=16896 floats) aliases hT floats
//   < 16896; chunk-31 hT reads are floats >= 248*72=17856 -> race-free.
// W2 in 8-k chunks (8KB), 2 buffers, ONE __syncthreads per chunk.
// smem 103.4KB -> 2 CTAs/SM.
// ---------------------------------------------------------------------------
#define HSTRIDE  72
#define LSTRIDE  264
#define XSTRIDE  12
#define SM_W1S   0          // 2048
#define SM_B1    2048       // 256
#define SM_B2    2304       // 256
#define SM_XS    2560       // 768 (64 rows * 12)
#define SM_HT    3328       // 18432 (256 k * 72); logits (64*264=16896) aliases
#define SM_W2    21760      // 2 bufs * 2048 (8 k * 256)
#define SM_FLOATS 25856     // 103424 bytes

__device__ __forceinline__ void ffma2(ull& d, ull a, ull b) {
  asm("fma.rn.f32x2 %0, %1, %2, %0;" : "+l"(d) : "l"(a), "l"(b));
}
__device__ __forceinline__ ull dup2(float v) {
  ull r;
  asm("mov.b64 %0, {%1, %1};" : "=l"(r) : "f"(v));
  return r;
}
__device__ __forceinline__ float2 unpack2(ull v) {
  float2 t;
  asm("mov.b64 {%0, %1}, %2;" : "=f"(t.x), "=f"(t.y) : "l"(v));
  return t;
}
__device__ __forceinline__ void cpasync16(float* s, const float* g) {
  unsigned sa = (unsigned)__cvta_generic_to_shared(s);
  asm volatile("cp.async.cg.shared.global [%0], [%1], 16;" :: "r"(sa), "l"(g));
}
__device__ __forceinline__ float fast_rcp(float d) {
  float r = __uint_as_float(0x7EF311C3u - __float_as_uint(d));
  r = r * (2.0f - d * r);
  r = r * (2.0f - d * r);
  r = r * (2.0f - d * r);
  return r;
}

__global__ void __launch_bounds__(256, 2)
mlp_kernel(const float* __restrict__ W1, const float* __restrict__ b1,
           const float* __restrict__ W2, const float* __restrict__ b2) {
  extern __shared__ float sm[];
  float* W1s    = sm + SM_W1S;
  float* b1s    = sm + SM_B1;
  float* b2s    = sm + SM_B2;
  float* xss    = sm + SM_XS;
  float* hT     = sm + SM_HT;
  float* logits = sm + SM_HT;   // alias: hT floats < 16896 dead by epilogue
  float* w2s    = sm + SM_W2;

  int tid = threadIdx.x, w = tid >> 5, l = tid & 31;
  int pass = blockIdx.y;
  int row0 = blockIdx.x * 64;
  const float* inp = (pass == 0) ? g_xmap : g_xp;

  double mapAcc = 0.0, netAcc = 0.0;
  unsigned int hitAcc = 0;

  for (int mm = 0; mm < MG; mm++) {
    __syncthreads();   // (a) prev-m logits/gather reads done before overwrite
    {
      const float4* w1p = (const float4*)(W1 + mm * 2048);
      float4* w1d = (float4*)W1s;
      w1d[tid] = w1p[tid];
      w1d[tid + 256] = w1p[tid + 256];
      b1s[tid] = b1[mm * 256 + tid];
      b2s[tid] = b2[mm * 256 + tid];
      int r = tid >> 2, c = tid & 3;
      float2 t = *(const float2*)(inp + (row0 + r) * NBITS + mm * 8 + 2 * c);
      *(float2*)(xss + r * XSTRIDE + 2 * c) = t;
    }
    __syncthreads();   // (b)

    // prefetch chunk 0 of W2 (overlaps GEMM1)
    {
      const float* src = W2 + mm * 65536;
      cpasync16(w2s + tid * 4, src + tid * 4);
      cpasync16(w2s + (tid + 256) * 4, src + (tid + 256) * 4);
      asm volatile("cp.async.commit_group;");
    }

    // ---- GEMM1: warp w computes rows [8w, 8w+8), all 256 k ----
#pragma unroll
    for (int kk = 0; kk < 8; kk++) {
      int k = kk * 32 + l;
      float w1c[8];
#pragma unroll
      for (int s = 0; s < 8; s++) w1c[s] = W1s[s * 256 + k];
      float bk = b1s[k];
      float* hp = hT + k * HSTRIDE + 8 * w;
#pragma unroll
      for (int rp = 0; rp < 4; rp++) {
        float h2[2];
#pragma unroll
        for (int u = 0; u < 2; u++) {
          int row = 8 * w + 2 * rp + u;
          const float* xb = xss + row * XSTRIDE;
          float4 xa = *(const float4*)(xb);
          float4 xc = *(const float4*)(xb + 4);
          float a = bk;
          a = fmaf(xa.x, w1c[0], a); a = fmaf(xa.y, w1c[1], a);
          a = fmaf(xa.z, w1c[2], a); a = fmaf(xa.w, w1c[3], a);
          a = fmaf(xc.x, w1c[4], a); a = fmaf(xc.y, w1c[5], a);
          a = fmaf(xc.z, w1c[6], a); a = fmaf(xc.w, w1c[7], a);
          float t = __expf(-a);
          float d = 1.0f + fminf(t, 1e30f);
          h2[u] = a * fast_rcp(d);
        }
        *(float2*)(hp + 2 * rp) = make_float2(h2[0], h2[1]);
      }
    }

    // ---- GEMM2: 8 rows x 256 cols per warp; 32 chunks of 8 k;
    //      one __syncthreads per chunk ----
    ull acc2[4][8];
#pragma unroll
    for (int i = 0; i < 4; i++)
#pragma unroll
      for (int j = 0; j < 8; j++) acc2[i][j] = 0ull;

    const float* wbase = w2s + 4 * l;
    const float* hbase = hT + 8 * w;

    for (int hc = 0; hc < 32; hc++) {
      asm volatile("cp.async.wait_group 0;");
      __syncthreads();   // chunk hc visible; buffer (hc+1)&1 retired by all

      if (hc + 1 < 32) {
        const float* src = W2 + mm * 65536 + (hc + 1) * 2048;
        float* dst = w2s + ((hc + 1) & 1) * 2048;
        cpasync16(dst + tid * 4, src + tid * 4);
        cpasync16(dst + (tid + 256) * 4, src + (tid + 256) * 4);
        asm volatile("cp.async.commit_group;");
      }

      const float* wch = wbase + (hc & 1) * 2048;
      const float* hb  = hbase + (hc * 8) * HSTRIDE;
#pragma unroll
      for (int kk2 = 0; kk2 < 8; kk2++) {
        float4 wa = *(const float4*)(wch + kk2 * 256);
        float4 wb = *(const float4*)(wch + kk2 * 256 + 128);
        ull wd0 = dup2(wa.x), wd1 = dup2(wa.y);
        ull wd2 = dup2(wa.z), wd3 = dup2(wa.w);
        ull wd4 = dup2(wb.x), wd5 = dup2(wb.y);
        ull wd6 = dup2(wb.z), wd7 = dup2(wb.w);
        const float* hk = hb + kk2 * HSTRIDE;
        ulonglong2 hA = *(const ulonglong2*)(hk);       // row pairs 0,1
        ulonglong2 hB = *(const ulonglong2*)(hk + 4);   // row pairs 2,3
        ffma2(acc2[0][0], hA.x, wd0); ffma2(acc2[0][1], hA.x, wd1);
        ffma2(acc2[0][2], hA.x, wd2); ffma2(acc2[0][3], hA.x, wd3);
        ffma2(acc2[0][4], hA.x, wd4); ffma2(acc2[0][5], hA.x, wd5);
        ffma2(acc2[0][6], hA.x, wd6); ffma2(acc2[0][7], hA.x, wd7);
        ffma2(acc2[1][0], hA.y, wd0); ffma2(acc2[1][1], hA.y, wd1);
        ffma2(acc2[1][2], hA.y, wd2); ffma2(acc2[1][3], hA.y, wd3);
        ffma2(acc2[1][4], hA.y, wd4); ffma2(acc2[1][5], hA.y, wd5);
        ffma2(acc2[1][6], hA.y, wd6); ffma2(acc2[1][7], hA.y, wd7);
        ffma2(acc2[2][0], hB.x, wd0); ffma2(acc2[2][1], hB.x, wd1);
        ffma2(acc2[2][2], hB.x, wd2); ffma2(acc2[2][3], hB.x, wd3);
        ffma2(acc2[2][4], hB.x, wd4); ffma2(acc2[2][5], hB.x, wd5);
        ffma2(acc2[2][6], hB.x, wd6); ffma2(acc2[2][7], hB.x, wd7);
        ffma2(acc2[3][0], hB.y, wd0); ffma2(acc2[3][1], hB.y, wd1);
        ffma2(acc2[3][2], hB.y, wd2); ffma2(acc2[3][3], hB.y, wd3);
        ffma2(acc2[3][4], hB.y, wd4); ffma2(acc2[3][5], hB.y, wd5);
        ffma2(acc2[3][6], hB.y, wd6); ffma2(acc2[3][7], hB.y, wd7);
      }
    }

    // ---- epilogue (warp-private rows; NO CTA barrier) ----
    float4 bA = *(const float4*)(b2s + 4 * l);
    float4 bB = *(const float4*)(b2s + 128 + 4 * l);

    for (int i = 0; i < 8; i++) {
      int p = i >> 1, hf = i & 1;
      int lrow = 8 * w + i;
      int grow = row0 + lrow;
      float v[8];
#pragma unroll
      for (int j = 0; j < 8; j++) {
        float2 t = unpack2(acc2[p][j]);
        float bj = (j < 4) ? ((const float*)&bA)[j] : ((const float*)&bB)[j - 4];
        v[j] = (hf ? t.y : t.x) + bj;
      }
      // write this row's logits (for gathers) — warp-private region
      *(float4*)(logits + lrow * LSTRIDE + 4 * l)       =
          make_float4(v[0], v[1], v[2], v[3]);
      *(float4*)(logits + lrow * LSTRIDE + 128 + 4 * l) =
          make_float4(v[4], v[5], v[6], v[7]);

      float mx = v[0]; int ai = 4 * l;
#pragma unroll
      for (int j = 1; j < 8; j++) {
        int col = (j < 4) ? (4 * l + j) : (128 + 4 * l + (j - 4));
        if (v[j] > mx) { mx = v[j]; ai = col; }
      }
      for (int o = 16; o; o >>= 1) {
        float vm = __shfl_xor_sync(0xffffffffu, mx, o);
        int   vi = __shfl_xor_sync(0xffffffffu, ai, o);
        if (vm > mx || (vm == mx && vi < ai)) { mx = vm; ai = vi; }
      }
      float se = 0.f;
#pragma unroll
      for (int j = 0; j < 8; j++) se += __expf(v[j] - mx);
      for (int o = 16; o; o >>= 1)
        se += __shfl_xor_sync(0xffffffffu, se, o);
      float lse = mx + __logf(se);
      __syncwarp();   // logits row visible within warp

      if (pass == 0) {
        if (l == 0) {
          int tgt = g_target[grow * MG + mm];
          mapAcc += (double)(lse - logits[lrow * LSTRIDE + tgt]);
          hitAcc += (ai == tgt) ? 1u : 0u;
        }
      } else {
        int K = g_K[grow];
        const unsigned char* al2 = g_act + grow * NC;
        double gs = 0.0;
        for (int ci = l; ci < K; ci += 32)
          gs += (double)logits[lrow * LSTRIDE + g_ct[al2[ci] * MG + mm]];
        for (int o = 16; o; o >>= 1)
          gs += __shfl_xor_sync(0xffffffffu, gs, o);
        if (l == 0) netAcc += (double)lse - gs / (double)K;
      }
      __syncwarp();
    }
  }

  if (l == 0) {
    if (pass == 0) {
      atomicAdd(&g_mapSum, mapAcc);
      atomicAdd(&g_hits, (unsigned long long)hitAcc);
    } else {
      atomicAdd(&g_netSum, netAcc);
    }
  }
}

// ---------------------------------------------------------------------------
// Kernel 5: finalize 5 scalars
// ---------------------------------------------------------------------------
__global__ void finalize_kernel(float* out) {
  if (threadIdx.x == 0) {
    double net = g_netSum / (double)NS;
    double map = g_mapSum / (double)NS;
    out[0] = (float)(net + map);
    out[1] = (float)net;
    out[2] = (float)map;
    out[3] = (float)((double)g_hits / ((double)NS * (double)MG));
    out[4] = (float)((double)g_hamSum / (double)g_actTot);
  }
}

// ---------------------------------------------------------------------------
extern "C" void kernel_launch(void* const* d_in, const int* in_sizes, int n_in,
                              void* d_out, int out_size) {
  const float* x    = (const float*)d_in[0];
  const int*   y    = (const int*)  d_in[1];
  const float* cen  = (const float*)d_in[2];
  const int*   perm = (const int*)  d_in[3];
  const void*  tmap = d_in[4];
  const void*  traw = d_in[5];
  const float* W1   = (const float*)d_in[6];
  const float* b1   = (const float*)d_in[7];
  const float* W2   = (const float*)d_in[8];
  const float* b2   = (const float*)d_in[9];
  float* out = (float*)d_out;

  uint32_t km0, km1, kr0, kr1;
  threefry2x32(0u, 1u, 0u, 0u, km0, km1);
  threefry2x32(0u, 1u, 0u, 1u, kr0, kr1);

  cudaFuncSetAttribute(mlp_kernel, cudaFuncAttributeMaxDynamicSharedMemorySize,
                       SM_FLOATS * 4);

  setup_kernel<<<1, 128>>>(cen, perm, (const unsigned char*)tmap,
                           (const unsigned char*)traw);
  prep_kernel<<<NS / 2, 256>>>(x, perm, tmap, traw, km0, km1, kr0, kr1);
  ham_kernel<<<NS / 8, 256>>>(y);
  dim3 grid(NS / 64, 2);
  mlp_kernel<<<grid, 256, SM_FLOATS * 4>>>(W1, b1, W2, b2);
  finalize_kernel<<<1, 32>>>(out);
  (void)in_sizes; (void)n_in; (void)out_size;
}

// round 17
// speedup vs baseline: 1.0412x; 1.0107x over previous
#include <cuda_runtime.h>
#include <cstdint>
#include <cstring>

#define NS    32768
#define NBITS 64
#define MG    8
#define HID   256
#define NC    100

typedef unsigned long long ull;

// ---------------------------------------------------------------------------
// Threefry-2x32, 20 rounds — bit-exact match of JAX's threefry2x32 primitive.
// ---------------------------------------------------------------------------
__host__ __device__ __forceinline__ void threefry2x32(
    uint32_t k0, uint32_t k1, uint32_t c0, uint32_t c1,
    uint32_t& o0, uint32_t& o1) {
  uint32_t ks2 = k0 ^ k1 ^ 0x1BD11BDAu;
  uint32_t x0 = c0 + k0;
  uint32_t x1 = c1 + k1;
#define TF_RND(r) { x0 += x1; x1 = (x1 << (r)) | (x1 >> (32 - (r))); x1 ^= x0; }
  TF_RND(13) TF_RND(15) TF_RND(26) TF_RND(6)
  x0 += k1;  x1 += ks2 + 1u;
  TF_RND(17) TF_RND(29) TF_RND(16) TF_RND(24)
  x0 += ks2; x1 += k0 + 2u;
  TF_RND(13) TF_RND(15) TF_RND(26) TF_RND(6)
  x0 += k0;  x1 += k1 + 3u;
  TF_RND(17) TF_RND(29) TF_RND(16) TF_RND(24)
  x0 += k1;  x1 += ks2 + 4u;
  TF_RND(13) TF_RND(15) TF_RND(26) TF_RND(6)
  x0 += ks2; x1 += k0 + 5u;
#undef TF_RND
  o0 = x0; o1 = x1;
}

// ---------------------------------------------------------------------------
// Device-global scratch
// ---------------------------------------------------------------------------
__device__ float g_xp  [NS * NBITS];
__device__ float g_xmap[NS * NBITS];
__device__ unsigned char g_target[NS * MG];
__device__ unsigned int  g_xbits[NS * 2];
__device__ int           g_K[NS];
__device__ unsigned char g_act[NS * NC];
__device__ unsigned char g_ct[NC * MG];
__device__ unsigned int  g_cbits[NC * 2];
__device__ double g_mapSum;
__device__ double g_netSum;
__device__ unsigned long long g_hits;
__device__ unsigned long long g_hamSum;
__device__ unsigned long long g_actTot;
__device__ int g_tmode;

__device__ __forceinline__ bool read_tpl(const void* p, int b) {
  if (g_tmode == 0) return ((const unsigned char*)p)[b] != 0;
  return ((const int*)p)[b] != 0;
}

// ---------------------------------------------------------------------------
// Kernel 1: accumulator init + template dtype detect + centroid prep
// ---------------------------------------------------------------------------
__global__ void setup_kernel(const float* __restrict__ cen,
                             const int* __restrict__ perm,
                             const unsigned char* tm, const unsigned char* tr) {
  __shared__ int permS[NBITS];
  int t = threadIdx.x;
  if (t < NBITS) permS[t] = perm[t];
  if (t == 0) {
    g_mapSum = 0.0; g_netSum = 0.0;
    g_hits = 0ull; g_hamSum = 0ull; g_actTot = 0ull;
    int has3F = 0, mis = 0;
    for (int i = 0; i < 64; i++) {
      unsigned char bm = tm[i], br = tr[i];
      if (bm == 0x3F || br == 0x3F) has3F = 1;
      if (i & 3) mis += (bm != 0) + (br != 0);
    }
    g_tmode = has3F ? 1 : (mis ? 0 : 1);
  }
  __syncthreads();
  if (t >= NC) return;
  unsigned int w0 = 0, w1 = 0;
  for (int b = 0; b < NBITS; b++) {
    bool bit = cen[t * NBITS + permS[b]] > 0.f;
    if (bit) { if (b < 32) w0 |= 1u << b; else w1 |= 1u << (b - 32); }
  }
  g_cbits[t * 2 + 0] = w0;
  g_cbits[t * 2 + 1] = w1;
  for (int m = 0; m < MG; m++) {
    unsigned int w = (m < 4) ? w0 : w1;
    g_ct[t * MG + m] = (unsigned char)((w >> ((m & 3) * 8)) & 0xffu);
  }
}

// ---------------------------------------------------------------------------
// Kernel 2: PRNG draws, stable argsort ranks, flips, targets, sign bits.
// ---------------------------------------------------------------------------
__global__ void prep_kernel(const float* __restrict__ x,
                            const int* __restrict__ perm,
                            const void* tmap, const void* traw,
                            uint32_t km0, uint32_t km1,
                            uint32_t kr0, uint32_t kr1) {
  __shared__ float xps[2][NBITS];
  __shared__ unsigned int us[2][2][NBITS];
  __shared__ int permS[NBITS];
  __shared__ int tposS[2][4];
  __shared__ int ranksS[2][2][4];
  __shared__ unsigned int rawb[2][2];
  __shared__ unsigned int xbw[2][2];

  int tid = threadIdx.x;
  if (tid < NBITS) permS[tid] = perm[tid];
  if (tid < 2) {
    const void* tp = (tid == 0) ? tmap : traw;
    int c = 0;
    for (int b = 0; b < NBITS; b++)
      if (read_tpl(tp, b)) { if (c < 4) tposS[tid][c] = b; c++; }
  }
  if (tid < 4) { rawb[tid >> 1][tid & 1] = 0u; xbw[tid >> 1][tid & 1] = 0u; }
  __syncthreads();

  int rid = tid >> 7;
  int sub = tid & 127;
  int op  = sub >> 6;
  int b   = sub & 63;
  int row = blockIdx.x * 2 + rid;

  if (op == 0) xps[rid][b] = x[row * NBITS + permS[b]];
  uint32_t k0 = op ? kr0 : km0;
  uint32_t k1 = op ? kr1 : km1;
  uint32_t o0, o1;
  threefry2x32(k0, k1, 0u, (uint32_t)(row * NBITS + b), o0, o1);
  us[rid][op][b] = (o0 ^ o1) >> 9;
  __syncthreads();

  if (b < 4) {
    int tpos = tposS[op][b];
    unsigned int ut = us[rid][op][tpos];
    int cnt = 0;
    for (int j = 0; j < NBITS; j++) {
      unsigned int uj = us[rid][op][j];
      cnt += (uj < ut) || (uj == ut && j < tpos);
    }
    ranksS[rid][op][b] = cnt;
  }
  __syncthreads();

  float v = xps[rid][b];
  bool flip = (b == ranksS[rid][op][0]) | (b == ranksS[rid][op][1]) |
              (b == ranksS[rid][op][2]) | (b == ranksS[rid][op][3]);
  if (op == 0) {
    g_xp  [row * NBITS + b] = v;
    g_xmap[row * NBITS + b] = flip ? -v : v;
    if (v > 0.f) atomicOr(&xbw[rid][b >> 5], 1u << (b & 31));
  } else {
    bool bit = flip ? (v < 0.f) : (v > 0.f);
    if (bit) atomicOr(&rawb[rid][b >> 5], 1u << (b & 31));
  }
  __syncthreads();

  if (op == 1 && b < MG) {
    unsigned int w = rawb[rid][b >> 2];
    g_target[row * MG + b] = (unsigned char)((w >> ((b & 3) * 8)) & 0xffu);
  }
  if (op == 0 && b < 2) g_xbits[row * 2 + b] = xbw[rid][b];
}

// ---------------------------------------------------------------------------
// Kernel 3: active-class compaction + exact hamming sums. 1 warp / row.
// ---------------------------------------------------------------------------
__global__ void ham_kernel(const int* __restrict__ y) {
  int tid = threadIdx.x, w = tid >> 5, l = tid & 31;
  int row = blockIdx.x * 8 + w;
  unsigned int xb0 = g_xbits[row * 2], xb1 = g_xbits[row * 2 + 1];
  int K = 0;
  unsigned long long hs = 0ull;
  for (int cb = 0; cb < 128; cb += 32) {
    int c = cb + l;
    bool act = (c < NC) && (y[row * NC + c] > 0);
    unsigned int msk = __ballot_sync(0xffffffffu, act);
    if (act) {
      int pos = K + __popc(msk & ((1u << l) - 1u));
      g_act[row * NC + pos] = (unsigned char)c;
      hs += (unsigned long long)(__popc(xb0 ^ g_cbits[c * 2]) +
                                 __popc(xb1 ^ g_cbits[c * 2 + 1]));
    }
    K += __popc(msk);
  }
  if (l == 0) g_K[row] = K;
  for (int o = 16; o; o >>= 1)
    hs += __shfl_xor_sync(0xffffffffu, hs, o);
  if (l == 0) {
    atomicAdd(&g_hamSum, hs);
    atomicAdd(&g_actTot, (unsigned long long)K);
  }
}

// ---------------------------------------------------------------------------
// Kernel 4: fused batched MLP + losses. FFMA2, 8 rows x 256 cols per warp,
// 16-k W2 chunks -> 19 barriers/m (was 34).
//
// CTA: 256 thr = 8 warps; 64 rows; 2 CTAs/SM. Warp w owns rows [8w, 8w+8)
//   and ALL 256 cols; lane l owns cols {4l..4l+3} U {128+4l..+3}.
// hT is warp-private ([k][8w..8w+8] written AND read by warp w); the only
//   shared resource in GEMM2 is the W2 buffer -> per-chunk barriers only.
// W2 in 16-k chunks (16KB), 2 buffers, ONE __syncthreads per chunk.
// One __syncthreads after the chunk loop makes the logits/hT alias safe
//   (all hT reads retired before any logits write).
// hT [k][row] stride 68 (16B-aligned); smem 113.0KB -> 2 CTAs/SM.
// ---------------------------------------------------------------------------
#define HSTRIDE  68
#define LSTRIDE  264
#define XSTRIDE  12
#define SM_W1S   0          // 2048
#define SM_B1    2048       // 256
#define SM_B2    2304       // 256
#define SM_XS    2560       // 768 (64 rows * 12)
#define SM_HT    3328       // 17408 (256 k * 68); logits (64*264=16896) aliases
#define SM_W2    20736      // 2 bufs * 4096 (16 k * 256)
#define SM_FLOATS 28928     // 115712 bytes

__device__ __forceinline__ void ffma2(ull& d, ull a, ull b) {
  asm("fma.rn.f32x2 %0, %1, %2, %0;" : "+l"(d) : "l"(a), "l"(b));
}
__device__ __forceinline__ ull dup2(float v) {
  ull r;
  asm("mov.b64 %0, {%1, %1};" : "=l"(r) : "f"(v));
  return r;
}
__device__ __forceinline__ float2 unpack2(ull v) {
  float2 t;
  asm("mov.b64 {%0, %1}, %2;" : "=f"(t.x), "=f"(t.y) : "l"(v));
  return t;
}
__device__ __forceinline__ void cpasync16(float* s, const float* g) {
  unsigned sa = (unsigned)__cvta_generic_to_shared(s);
  asm volatile("cp.async.cg.shared.global [%0], [%1], 16;" :: "r"(sa), "l"(g));
}
__device__ __forceinline__ float fast_rcp(float d) {
  float r = __uint_as_float(0x7EF311C3u - __float_as_uint(d));
  r = r * (2.0f - d * r);
  r = r * (2.0f - d * r);
  r = r * (2.0f - d * r);
  return r;
}

__global__ void __launch_bounds__(256, 2)
mlp_kernel(const float* __restrict__ W1, const float* __restrict__ b1,
           const float* __restrict__ W2, const float* __restrict__ b2) {
  extern __shared__ float sm[];
  float* W1s    = sm + SM_W1S;
  float* b1s    = sm + SM_B1;
  float* b2s    = sm + SM_B2;
  float* xss    = sm + SM_XS;
  float* hT     = sm + SM_HT;
  float* logits = sm + SM_HT;   // alias: safe via post-GEMM2 barrier
  float* w2s    = sm + SM_W2;

  int tid = threadIdx.x, w = tid >> 5, l = tid & 31;
  int pass = blockIdx.y;
  int row0 = blockIdx.x * 64;
  const float* inp = (pass == 0) ? g_xmap : g_xp;

  double mapAcc = 0.0, netAcc = 0.0;
  unsigned int hitAcc = 0;

  for (int mm = 0; mm < MG; mm++) {
    __syncthreads();   // (a) prev-m logits/gather reads done before overwrite
    {
      const float4* w1p = (const float4*)(W1 + mm * 2048);
      float4* w1d = (float4*)W1s;
      w1d[tid] = w1p[tid];
      w1d[tid + 256] = w1p[tid + 256];
      b1s[tid] = b1[mm * 256 + tid];
      b2s[tid] = b2[mm * 256 + tid];
      int r = tid >> 2, c = tid & 3;
      float2 t = *(const float2*)(inp + (row0 + r) * NBITS + mm * 8 + 2 * c);
      *(float2*)(xss + r * XSTRIDE + 2 * c) = t;
    }
    __syncthreads();   // (b)

    // prefetch chunk 0 of W2 (overlaps GEMM1): 16 k x 256 = 4096 floats
    {
      const float* src = W2 + mm * 65536;
#pragma unroll
      for (int q = 0; q < 4; q++)
        cpasync16(w2s + (tid + q * 256) * 4, src + (tid + q * 256) * 4);
      asm volatile("cp.async.commit_group;");
    }

    // ---- GEMM1: warp w computes rows [8w, 8w+8), all 256 k ----
#pragma unroll
    for (int kk = 0; kk < 8; kk++) {
      int k = kk * 32 + l;
      float w1c[8];
#pragma unroll
      for (int s = 0; s < 8; s++) w1c[s] = W1s[s * 256 + k];
      float bk = b1s[k];
      float* hp = hT + k * HSTRIDE + 8 * w;
#pragma unroll
      for (int rp = 0; rp < 4; rp++) {
        float h2[2];
#pragma unroll
        for (int u = 0; u < 2; u++) {
          int row = 8 * w + 2 * rp + u;
          const float* xb = xss + row * XSTRIDE;
          float4 xa = *(const float4*)(xb);
          float4 xc = *(const float4*)(xb + 4);
          float a = bk;
          a = fmaf(xa.x, w1c[0], a); a = fmaf(xa.y, w1c[1], a);
          a = fmaf(xa.z, w1c[2], a); a = fmaf(xa.w, w1c[3], a);
          a = fmaf(xc.x, w1c[4], a); a = fmaf(xc.y, w1c[5], a);
          a = fmaf(xc.z, w1c[6], a); a = fmaf(xc.w, w1c[7], a);
          float t = __expf(-a);
          float d = 1.0f + fminf(t, 1e30f);
          h2[u] = a * fast_rcp(d);
        }
        *(float2*)(hp + 2 * rp) = make_float2(h2[0], h2[1]);
      }
    }

    // ---- GEMM2: 8 rows x 256 cols per warp; 16 chunks of 16 k ----
    ull acc2[4][8];
#pragma unroll
    for (int i = 0; i < 4; i++)
#pragma unroll
      for (int j = 0; j < 8; j++) acc2[i][j] = 0ull;

    const float* wbase = w2s + 4 * l;
    const float* hbase = hT + 8 * w;

    for (int hc = 0; hc < 16; hc++) {
      asm volatile("cp.async.wait_group 0;");
      __syncthreads();   // chunk hc visible; buffer (hc+1)&1 retired by all

      if (hc + 1 < 16) {
        const float* src = W2 + mm * 65536 + (hc + 1) * 4096;
        float* dst = w2s + ((hc + 1) & 1) * 4096;
#pragma unroll
        for (int q = 0; q < 4; q++)
          cpasync16(dst + (tid + q * 256) * 4, src + (tid + q * 256) * 4);
        asm volatile("cp.async.commit_group;");
      }

      const float* wch = wbase + (hc & 1) * 4096;
      const float* hb  = hbase + (hc * 16) * HSTRIDE;
#pragma unroll 8
      for (int kk2 = 0; kk2 < 16; kk2++) {
        float4 wa = *(const float4*)(wch + kk2 * 256);
        float4 wb = *(const float4*)(wch + kk2 * 256 + 128);
        ull wd0 = dup2(wa.x), wd1 = dup2(wa.y);
        ull wd2 = dup2(wa.z), wd3 = dup2(wa.w);
        ull wd4 = dup2(wb.x), wd5 = dup2(wb.y);
        ull wd6 = dup2(wb.z), wd7 = dup2(wb.w);
        const float* hk = hb + kk2 * HSTRIDE;
        ulonglong2 hA = *(const ulonglong2*)(hk);       // row pairs 0,1
        ulonglong2 hB = *(const ulonglong2*)(hk + 4);   // row pairs 2,3
        ffma2(acc2[0][0], hA.x, wd0); ffma2(acc2[0][1], hA.x, wd1);
        ffma2(acc2[0][2], hA.x, wd2); ffma2(acc2[0][3], hA.x, wd3);
        ffma2(acc2[0][4], hA.x, wd4); ffma2(acc2[0][5], hA.x, wd5);
        ffma2(acc2[0][6], hA.x, wd6); ffma2(acc2[0][7], hA.x, wd7);
        ffma2(acc2[1][0], hA.y, wd0); ffma2(acc2[1][1], hA.y, wd1);
        ffma2(acc2[1][2], hA.y, wd2); ffma2(acc2[1][3], hA.y, wd3);
        ffma2(acc2[1][4], hA.y, wd4); ffma2(acc2[1][5], hA.y, wd5);
        ffma2(acc2[1][6], hA.y, wd6); ffma2(acc2[1][7], hA.y, wd7);
        ffma2(acc2[2][0], hB.x, wd0); ffma2(acc2[2][1], hB.x, wd1);
        ffma2(acc2[2][2], hB.x, wd2); ffma2(acc2[2][3], hB.x, wd3);
        ffma2(acc2[2][4], hB.x, wd4); ffma2(acc2[2][5], hB.x, wd5);
        ffma2(acc2[2][6], hB.x, wd6); ffma2(acc2[2][7], hB.x, wd7);
        ffma2(acc2[3][0], hB.y, wd0); ffma2(acc2[3][1], hB.y, wd1);
        ffma2(acc2[3][2], hB.y, wd2); ffma2(acc2[3][3], hB.y, wd3);
        ffma2(acc2[3][4], hB.y, wd4); ffma2(acc2[3][5], hB.y, wd5);
        ffma2(acc2[3][6], hB.y, wd6); ffma2(acc2[3][7], hB.y, wd7);
      }
    }

    __syncthreads();   // (c) all hT reads retired -> logits alias safe

    // ---- epilogue: logits + reductions (rows warp-private) ----
    float4 bA = *(const float4*)(b2s + 4 * l);
    float4 bB = *(const float4*)(b2s + 128 + 4 * l);

    for (int i = 0; i < 8; i++) {
      int p = i >> 1, hf = i & 1;
      int lrow = 8 * w + i;
      int grow = row0 + lrow;
      float v[8];
#pragma unroll
      for (int j = 0; j < 8; j++) {
        float2 t = unpack2(acc2[p][j]);
        float bj = (j < 4) ? ((const float*)&bA)[j] : ((const float*)&bB)[j - 4];
        v[j] = (hf ? t.y : t.x) + bj;
      }
      *(float4*)(logits + lrow * LSTRIDE + 4 * l)       =
          make_float4(v[0], v[1], v[2], v[3]);
      *(float4*)(logits + lrow * LSTRIDE + 128 + 4 * l) =
          make_float4(v[4], v[5], v[6], v[7]);

      float mx = v[0]; int ai = 4 * l;
#pragma unroll
      for (int j = 1; j < 8; j++) {
        int col = (j < 4) ? (4 * l + j) : (128 + 4 * l + (j - 4));
        if (v[j] > mx) { mx = v[j]; ai = col; }
      }
      for (int o = 16; o; o >>= 1) {
        float vm = __shfl_xor_sync(0xffffffffu, mx, o);
        int   vi = __shfl_xor_sync(0xffffffffu, ai, o);
        if (vm > mx || (vm == mx && vi < ai)) { mx = vm; ai = vi; }
      }
      float se = 0.f;
#pragma unroll
      for (int j = 0; j < 8; j++) se += __expf(v[j] - mx);
      for (int o = 16; o; o >>= 1)
        se += __shfl_xor_sync(0xffffffffu, se, o);
      float lse = mx + __logf(se);
      __syncwarp();   // logits row visible within warp

      if (pass == 0) {
        if (l == 0) {
          int tgt = g_target[grow * MG + mm];
          mapAcc += (double)(lse - logits[lrow * LSTRIDE + tgt]);
          hitAcc += (ai == tgt) ? 1u : 0u;
        }
      } else {
        int K = g_K[grow];
        const unsigned char* al2 = g_act + grow * NC;
        double gs = 0.0;
        for (int ci = l; ci < K; ci += 32)
          gs += (double)logits[lrow * LSTRIDE + g_ct[al2[ci] * MG + mm]];
        for (int o = 16; o; o >>= 1)
          gs += __shfl_xor_sync(0xffffffffu, gs, o);
        if (l == 0) netAcc += (double)lse - gs / (double)K;
      }
      __syncwarp();
    }
  }

  if (l == 0) {
    if (pass == 0) {
      atomicAdd(&g_mapSum, mapAcc);
      atomicAdd(&g_hits, (unsigned long long)hitAcc);
    } else {
      atomicAdd(&g_netSum, netAcc);
    }
  }
}

// ---------------------------------------------------------------------------
// Kernel 5: finalize 5 scalars
// ---------------------------------------------------------------------------
__global__ void finalize_kernel(float* out) {
  if (threadIdx.x == 0) {
    double net = g_netSum / (double)NS;
    double map = g_mapSum / (double)NS;
    out[0] = (float)(net + map);
    out[1] = (float)net;
    out[2] = (float)map;
    out[3] = (float)((double)g_hits / ((double)NS * (double)MG));
    out[4] = (float)((double)g_hamSum / (double)g_actTot);
  }
}

// ---------------------------------------------------------------------------
extern "C" void kernel_launch(void* const* d_in, const int* in_sizes, int n_in,
                              void* d_out, int out_size) {
  const float* x    = (const float*)d_in[0];
  const int*   y    = (const int*)  d_in[1];
  const float* cen  = (const float*)d_in[2];
  const int*   perm = (const int*)  d_in[3];
  const void*  tmap = d_in[4];
  const void*  traw = d_in[5];
  const float* W1   = (const float*)d_in[6];
  const float* b1   = (const float*)d_in[7];
  const float* W2   = (const float*)d_in[8];
  const float* b2   = (const float*)d_in[9];
  float* out = (float*)d_out;

  uint32_t km0, km1, kr0, kr1;
  threefry2x32(0u, 1u, 0u, 0u, km0, km1);
  threefry2x32(0u, 1u, 0u, 1u, kr0, kr1);

  cudaFuncSetAttribute(mlp_kernel, cudaFuncAttributeMaxDynamicSharedMemorySize,
                       SM_FLOATS * 4);

  setup_kernel<<<1, 128>>>(cen, perm, (const unsigned char*)tmap,
                           (const unsigned char*)traw);
  prep_kernel<<<NS / 2, 256>>>(x, perm, tmap, traw, km0, km1, kr0, kr1);
  ham_kernel<<<NS / 8, 256>>>(y);
  dim3 grid(NS / 64, 2);
  mlp_kernel<<<grid, 256, SM_FLOATS * 4>>>(W1, b1, W2, b2);
  finalize_kernel<<<1, 32>>>(out);
  (void)in_sizes; (void)n_in; (void)out_size;
}